// round 10
// baseline (speedup 1.0000x reference)
#include <cuda_runtime.h>
#include <cuda_bf16.h>
#include <stdint.h>

// ============================================================================
// StressNN on GB300 (sm_103a, plain sm_103 PTX target -> HMMA path)
//   R10: C->A register chaining. Warp tile m16 x n128: each warp owns 16 rows
//   entirely, so layer-l accumulators convert IN REGISTERS (gelu + bf16 split)
//   into layer-(l+1) A fragments (acc m16n8 layout == A m16k16 layout).
//   Zero activation smem traffic after layer 0; W double-buffered (1 sync/layer).
// ============================================================================

#define TILE_M   192
#define THREADS  384

#define OFF_W0     0
#define OFF_W1     65536
#define OFF_X      131072
#define XCHUNK     24576       // 192 rows * 128B
#define XLO_DELTA  49152
#define WCHUNK     16384
#define WLO_DELTA  32768
#define SMEM_TOTAL 229376

__device__ __align__(16) unsigned char g_wimg[7 * 65536];
__device__ float g_bias[7 * 128];

// ---------------------------------------------------------------------------
__device__ __forceinline__ uint32_t smem_u32(const void* p) {
    uint32_t a;
    asm("{ .reg .u64 t; cvta.to.shared.u64 t, %1; cvt.u32.u64 %0, t; }"
        : "=r"(a) : "l"(p));
    return a;
}

#define LDSM_X4(r0, r1, r2, r3, a) \
    asm volatile("ldmatrix.sync.aligned.m8n8.x4.shared.b16 {%0,%1,%2,%3}, [%4];" \
                 : "=r"(r0), "=r"(r1), "=r"(r2), "=r"(r3) : "r"(a))

#define MMA_BF16(c, a, b) \
    asm volatile("mma.sync.aligned.m16n8k16.row.col.f32.bf16.bf16.f32 " \
                 "{%0,%1,%2,%3},{%4,%5,%6,%7},{%8,%9},{%0,%1,%2,%3};" \
                 : "+f"((c)[0]), "+f"((c)[1]), "+f"((c)[2]), "+f"((c)[3]) \
                 : "r"((a)[0]), "r"((a)[1]), "r"((a)[2]), "r"((a)[3]), \
                   "r"((b)[0]), "r"((b)[1]))

#define CP_ASYNC16(dst, src) \
    asm volatile("cp.async.cg.shared.global [%0], [%1], 16;" \
                 :: "r"(dst), "l"(src) : "memory")
#define CP_COMMIT() asm volatile("cp.async.commit_group;" ::: "memory")
#define CP_WAIT0()  asm volatile("cp.async.wait_group 0;" ::: "memory")

#define STS32(a, v) \
    asm volatile("st.shared.b32 [%0], %1;" :: "r"(a), "r"(v) : "memory")

// split two floats into bf16x2 hi word + bf16x2 lo word
__device__ __forceinline__ void split_pack(float a0, float a1,
                                           uint32_t& hi, uint32_t& lo) {
    uint32_t h;
    asm("cvt.rn.bf16x2.f32 %0, %1, %2;" : "=r"(h) : "f"(a1), "f"(a0));
    float h0 = __uint_as_float(h << 16);
    float h1 = __uint_as_float(h & 0xFFFF0000u);
    float l0 = a0 - h0;
    float l1 = a1 - h1;
    asm("cvt.rn.bf16x2.f32 %0, %1, %2;" : "=r"(lo) : "f"(l1), "f"(l0));
    hi = h;
}

// erf via Abramowitz-Stegun 7.1.26 (|eps| <= 1.5e-7), branch-free
__device__ __forceinline__ float erf_fast(float x) {
    float ax = fabsf(x);
    float t = __frcp_rn(fmaf(0.3275911f, ax, 1.0f));
    float y = t * fmaf(t, fmaf(t, fmaf(t, fmaf(t, 1.061405429f, -1.453152027f),
                                       1.421413741f), -0.284496736f), 0.254829592f);
    float r = 1.0f - y * __expf(-ax * ax);
    return copysignf(r, x);
}

__device__ __forceinline__ float gelu_exact(float x) {
    return 0.5f * x * (1.0f + erf_fast(x * 0.70710678118654752f));
}

// ---------------------------------------------------------------------------
// prep kernel: bf16 hi/lo split, pre-swizzled SW128 W^T tile images + bias
// ---------------------------------------------------------------------------
__global__ void prep_all(const float* __restrict__ w1, const float* __restrict__ w2,
                         const float* __restrict__ w3, const float* __restrict__ w4,
                         const float* __restrict__ w5, const float* __restrict__ w6,
                         const float* __restrict__ w7,
                         const float* __restrict__ b1, const float* __restrict__ b2,
                         const float* __restrict__ b3, const float* __restrict__ b4,
                         const float* __restrict__ b5, const float* __restrict__ b6,
                         const float* __restrict__ b7) {
    int idx = blockIdx.x * blockDim.x + threadIdx.x;
    if (idx < 7 * 16384) {
        int l = idx >> 14;
        int rem = idx & 16383;
        int n = rem >> 7;
        int k = rem & 127;
        int K = (l == 0) ? 89 : 128;
        int N = (l == 6) ? 9 : 128;
        const float* w;
        switch (l) {
            case 0: w = w1; break; case 1: w = w2; break; case 2: w = w3; break;
            case 3: w = w4; break; case 4: w = w5; break; case 5: w = w6; break;
            default: w = w7; break;
        }
        float v = 0.f;
        if (k < K && n < N) v = w[k * N + n];
        __nv_bfloat16 hi = __float2bfloat16(v);
        __nv_bfloat16 lo = __float2bfloat16(v - __bfloat162float(hi));
        size_t off = (size_t)l * 65536 + (size_t)(k >> 6) * 16384 +
                     (uint32_t)(n * 128 + (((k & 63) * 2) ^ ((n & 7) << 4)));
        *(__nv_bfloat16*)(g_wimg + off)         = hi;
        *(__nv_bfloat16*)(g_wimg + off + 32768) = lo;
    }
    if (idx < 7 * 128) {
        int l = idx >> 7;
        int n = idx & 127;
        const float* b;
        switch (l) {
            case 0: b = b1; break; case 1: b = b2; break; case 2: b = b3; break;
            case 3: b = b4; break; case 4: b = b5; break; case 5: b = b6; break;
            default: b = b7; break;
        }
        int N = (l == 6) ? 9 : 128;
        g_bias[idx] = (n < N) ? b[n] : 0.f;
    }
}

// ---------------------------------------------------------------------------
__device__ __forceinline__ void init_bias(float (&acc)[16][4],
                                          const float* gb, int tid4) {
    #pragma unroll
    for (int nt = 0; nt < 16; ++nt) {
        float b0 = __ldg(gb + nt * 8 + 2 * tid4);
        float b1 = __ldg(gb + nt * 8 + 2 * tid4 + 1);
        acc[nt][0] = b0; acc[nt][1] = b1;
        acc[nt][2] = b0; acc[nt][3] = b1;
    }
}

// full-width MMA: warp computes its 16 rows x all 128 cols; B streamed via LDSM
template <int KS>
__device__ __forceinline__ void mma_layer_reg(float (&acc)[16][4],
                                              const uint32_t (&ah)[8][4],
                                              const uint32_t (&al)[8][4],
                                              uint32_t wbuf, uint32_t wrowoff,
                                              uint32_t kB, uint32_t nswz) {
    #pragma unroll
    for (int ks = 0; ks < KS; ++ks) {
        uint32_t koffB = ((((uint32_t)ks * 16 + kB) & 63) << 1) ^ nswz;
        uint32_t kbase = wbuf + (uint32_t)(ks >> 2) * WCHUNK + koffB + wrowoff;
        #pragma unroll
        for (int ntp = 0; ntp < 8; ++ntp) {
            uint32_t ba = kbase + (uint32_t)ntp * 2048;
            uint32_t bh[4], bl[4];
            LDSM_X4(bh[0], bh[1], bh[2], bh[3], ba);
            LDSM_X4(bl[0], bl[1], bl[2], bl[3], ba + WLO_DELTA);
            MMA_BF16(acc[2 * ntp],     ah[ks], bh);
            MMA_BF16(acc[2 * ntp],     ah[ks], bl);
            MMA_BF16(acc[2 * ntp],     al[ks], bh);
            MMA_BF16(acc[2 * ntp + 1], ah[ks], bh + 2);
            MMA_BF16(acc[2 * ntp + 1], ah[ks], bl + 2);
            MMA_BF16(acc[2 * ntp + 1], al[ks], bh + 2);
        }
    }
}

// acc (post-layer) -> gelu -> next layer's A fragments, all in registers.
// acc m16n8 layout == A m16k16 layout: ntile 2kk -> k-low half, 2kk+1 -> k-high.
__device__ __forceinline__ void epi_to_frags(const float (&acc)[16][4],
                                             uint32_t (&ah)[8][4],
                                             uint32_t (&al)[8][4]) {
    #pragma unroll
    for (int kk = 0; kk < 8; ++kk) {
        #pragma unroll
        for (int h = 0; h < 2; ++h) {
            const float* a = acc[2 * kk + h];
            float g0 = gelu_exact(a[0]);
            float g1 = gelu_exact(a[1]);
            float g2 = gelu_exact(a[2]);
            float g3 = gelu_exact(a[3]);
            split_pack(g0, g1, ah[kk][2 * h],     al[kk][2 * h]);
            split_pack(g2, g3, ah[kk][2 * h + 1], al[kk][2 * h + 1]);
        }
    }
}

// ---------------------------------------------------------------------------
// main fused kernel: 1 CTA = 192 particles; 12 warps, warp w owns rows 16w..16w+15
// ---------------------------------------------------------------------------
__global__ void __launch_bounds__(THREADS, 1)
stress_main(const float* __restrict__ F, const float* __restrict__ C,
            const int* __restrict__ traj_id, const float* __restrict__ latent,
            float* __restrict__ out, int Bn) {
    extern __shared__ char smem[];
    const uint32_t sb = smem_u32(smem);
    const int t    = threadIdx.x;
    const int wid  = t >> 5;
    const int lane = t & 31;
    const int g    = lane >> 2;
    const int tid4 = lane & 3;

    const size_t base = (size_t)blockIdx.x * TILE_M;
    const int valid = min(TILE_M, Bn - (int)base);

    // prefetch W0 into buf0
    {
        const char* wsrc = (const char*)g_wimg;
        for (int i = t; i < 4096; i += THREADS)
            CP_ASYNC16(sb + OFF_W0 + (uint32_t)i * 16, wsrc + (size_t)i * 16);
        CP_COMMIT();
    }

    // stage F, C coalesced through X scratch
    {
        const float* Fg = F + base * 9;
        const float* Cg = C + base * 9;
        float* s1 = (float*)(smem + OFF_X);
        float* s2 = (float*)(smem + OFF_X + 8192);
        int lim = valid * 9;
        for (int i = t; i < lim; i += THREADS) { s1[i] = Fg[i]; s2[i] = Cg[i]; }
    }
    __syncthreads();

    float f[9], c9[9];
    if (t < TILE_M) {
        if (t < valid) {
            const float* s1 = (const float*)(smem + OFF_X);
            const float* s2 = (const float*)(smem + OFF_X + 8192);
            #pragma unroll
            for (int i = 0; i < 9; ++i) { f[i] = s1[t * 9 + i]; c9[i] = s2[t * 9 + i]; }
        } else {
            #pragma unroll
            for (int i = 0; i < 9; ++i) { f[i] = (i % 4 == 0) ? 1.f : 0.f; c9[i] = 0.f; }
        }
    }
    __syncthreads();

    // ---- features: thread t (<192) owns row t; write swizzled X hi/lo ----
    if (t < TILE_M) {
        const int traj = traj_id[0];
        const float* latp = latent + (size_t)traj * 64;
        float fe[16];
        #pragma unroll
        for (int i = 0; i < 3; ++i)
            #pragma unroll
            for (int k = 0; k < 3; ++k)
                fe[i * 3 + k] = f[i*3+0]*f[k*3+0] + f[i*3+1]*f[k*3+1] + f[i*3+2]*f[k*3+2];
        float det = f[0]*(f[4]*f[8]-f[5]*f[7]) - f[1]*(f[3]*f[8]-f[5]*f[6])
                  + f[2]*(f[3]*f[7]-f[4]*f[6]);
        float J  = fmaxf(det, 1e-6f);
        float J1 = fmaxf(f[0], 1e-6f);
        float a00 = fe[0], a01 = fe[1], a02 = fe[2], a11 = fe[4], a12 = fe[5], a22 = fe[8];
        float q  = (a00 + a11 + a22) * (1.f / 3.f);
        float p1 = a01*a01 + a02*a02 + a12*a12;
        float d0 = a00 - q, d1 = a11 - q, d2 = a22 - q;
        float p2 = d0*d0 + d1*d1 + d2*d2 + 2.f*p1;
        float pp = sqrtf(fmaxf(p2 * (1.f / 6.f), 0.f));
        float ip = 1.f / fmaxf(pp, 1e-20f);
        float b00 = d0*ip, b01 = a01*ip, b02 = a02*ip;
        float b11 = d1*ip, b12 = a12*ip, b22 = d2*ip;
        float detB = b00*(b11*b22 - b12*b12) - b01*(b01*b22 - b12*b02)
                   + b02*(b01*b12 - b11*b02);
        float r = fminf(fmaxf(0.5f * detB, -1.f), 1.f);
        float phi = acosf(r) * (1.f / 3.f);
        float e1 = q + 2.f * pp * cosf(phi);
        float e3 = q + 2.f * pp * cosf(phi + 2.0943951023931953f);
        float e2 = 3.f * q - e1 - e3;
        fe[9]  = logf(J);
        fe[10] = sqrtf(fmaxf(e1, 0.f));
        fe[11] = sqrtf(fmaxf(e2, 0.f));
        fe[12] = sqrtf(fmaxf(e3, 0.f));
        fe[13] = J;
        fe[14] = logf(J1);
        fe[15] = J1;

        uint32_t rowbase = sb + OFF_X + (uint32_t)t * 128;
        uint32_t rsw0 = (uint32_t)(t & 7) << 4;
        #pragma unroll
        for (int n = 0; n < 96; n += 2) {   // only K=96 (89 padded) needed
            #define CVAL(nn) ((nn) < 16 ? fe[(nn)] : ((nn) < 25 ? c9[(nn)-16] : \
                              ((nn) < 89 ? __ldg(latp + (nn)-25) : 0.f)))
            float v0 = CVAL(n);
            float v1 = CVAL(n + 1);
            #undef CVAL
            uint32_t hi, lo;
            split_pack(v0, v1, hi, lo);
            uint32_t a = rowbase + (uint32_t)((n >> 6) * XCHUNK)
                       + (((uint32_t)(n & 63) << 1) ^ rsw0);
            STS32(a, hi);
            STS32(a + XLO_DELTA, lo);
        }
    }
    CP_WAIT0();
    __syncthreads();   // X + W0 ready

    // ---- per-lane constants ----
    const uint32_t nswz    = (uint32_t)(lane & 7) << 4;
    const uint32_t kB      = (uint32_t)(lane & 8);
    const uint32_t kA      = (lane & 16) ? 8u : 0u;
    const uint32_t wrowoff = (uint32_t)((lane & 7) + (((uint32_t)lane >> 4) << 3)) * 128;
    const uint32_t abase   = sb + OFF_X + (uint32_t)(wid * 16 + (lane & 15)) * 128;

    uint32_t ah[8][4], al[8][4];
    float acc[16][4];

    // ---- layer 0: A fragments from X (once), then never touch X again ----
    #pragma unroll
    for (int ks = 0; ks < 6; ++ks) {
        uint32_t koffA = ((((uint32_t)ks * 16 + kA) & 63) << 1) ^ nswz;
        uint32_t aa = abase + (uint32_t)(ks >> 2) * XCHUNK + koffA;
        LDSM_X4(ah[ks][0], ah[ks][1], ah[ks][2], ah[ks][3], aa);
        LDSM_X4(al[ks][0], al[ks][1], al[ks][2], al[ks][3], aa + XLO_DELTA);
    }
    // prefetch W1 into buf1 (disjoint from X; no sync needed)
    {
        const char* wsrc = (const char*)(g_wimg + 65536);
        for (int i = t; i < 4096; i += THREADS)
            CP_ASYNC16(sb + OFF_W1 + (uint32_t)i * 16, wsrc + (size_t)i * 16);
        CP_COMMIT();
    }
    init_bias(acc, g_bias, tid4);
    mma_layer_reg<6>(acc, ah, al, sb + OFF_W0, wrowoff, kB, nswz);
    epi_to_frags(acc, ah, al);

    // ---- layers 1..5: A in registers, W double-buffered, 1 sync/layer ----
    #pragma unroll 1
    for (int l = 1; l < 6; ++l) {
        CP_WAIT0();
        __syncthreads();   // W(l) arrived; all warps done reading W(l-1)
        {
            const char* wsrc = (const char*)(g_wimg + (size_t)(l + 1) * 65536);
            uint32_t wdst = sb + (uint32_t)(((l + 1) & 1) << 16);
            for (int i = t; i < 4096; i += THREADS)
                CP_ASYNC16(wdst + (uint32_t)i * 16, wsrc + (size_t)i * 16);
            CP_COMMIT();
        }
        init_bias(acc, g_bias + l * 128, tid4);
        mma_layer_reg<8>(acc, ah, al, sb + (uint32_t)((l & 1) << 16),
                         wrowoff, kB, nswz);
        epi_to_frags(acc, ah, al);
    }

    // ---- layer 6 (N=16; every warp computes its own 16 rows) ----
    CP_WAIT0();
    __syncthreads();   // W6 in buf0
    float acc6[2][4];
    {
        const float* gb = g_bias + 6 * 128;
        #pragma unroll
        for (int nt = 0; nt < 2; ++nt) {
            float b0 = __ldg(gb + nt * 8 + 2 * tid4);
            float b1 = __ldg(gb + nt * 8 + 2 * tid4 + 1);
            acc6[nt][0] = b0; acc6[nt][1] = b1;
            acc6[nt][2] = b0; acc6[nt][3] = b1;
        }
        uint32_t wbuf = sb + OFF_W0;
        #pragma unroll
        for (int ks = 0; ks < 8; ++ks) {
            uint32_t koffB = ((((uint32_t)ks * 16 + kB) & 63) << 1) ^ nswz;
            uint32_t ba = wbuf + (uint32_t)(ks >> 2) * WCHUNK + koffB + wrowoff;
            uint32_t bh[4], bl[4];
            LDSM_X4(bh[0], bh[1], bh[2], bh[3], ba);
            LDSM_X4(bl[0], bl[1], bl[2], bl[3], ba + WLO_DELTA);
            MMA_BF16(acc6[0], ah[ks], bh);
            MMA_BF16(acc6[0], ah[ks], bl);
            MMA_BF16(acc6[0], al[ks], bh);
            MMA_BF16(acc6[1], ah[ks], bh + 2);
            MMA_BF16(acc6[1], ah[ks], bl + 2);
            MMA_BF16(acc6[1], al[ks], bh + 2);
        }
    }

    // ---- stage cols 0..8 into smem (X region is dead), symmetrize, store ----
    float* stag = (float*)(smem + OFF_X);           // [192][12]
    {
        int r0 = wid * 16 + g;
        #pragma unroll
        for (int nt = 0; nt < 2; ++nt) {
            int c = nt * 8 + tid4 * 2;
            if (c < 9) {
                stag[r0 * 12 + c]       = acc6[nt][0];
                stag[(r0 + 8) * 12 + c] = acc6[nt][2];
            }
            if (c + 1 < 9) {
                stag[r0 * 12 + c + 1]       = acc6[nt][1];
                stag[(r0 + 8) * 12 + c + 1] = acc6[nt][3];
            }
        }
    }
    __syncthreads();

    float* stag2 = (float*)(smem + OFF_X + 12288);  // [192*9]
    if (t < TILE_M) {
        float o[9];
        #pragma unroll
        for (int j = 0; j < 9; ++j) o[j] = stag[t * 12 + j];
        float s01 = 0.5f * (o[1] + o[3]);
        float s02 = 0.5f * (o[2] + o[6]);
        float s12 = 0.5f * (o[5] + o[7]);
        float* d = stag2 + t * 9;
        d[0] = o[0]; d[1] = s01; d[2] = s02;
        d[3] = s01;  d[4] = o[4]; d[5] = s12;
        d[6] = s02;  d[7] = s12;  d[8] = o[8];
    }
    __syncthreads();
    {
        float* og = out + base * 9;
        int lim = valid * 9;
        for (int i = t; i < lim; i += THREADS) og[i] = stag2[i];
    }
}

// ---------------------------------------------------------------------------
extern "C" void kernel_launch(void* const* d_in, const int* in_sizes, int n_in,
                              void* d_out, int out_size) {
    const float* F      = (const float*)d_in[0];
    const float* C      = (const float*)d_in[1];
    const int*   traj   = (const int*)d_in[2];
    const float* latent = (const float*)d_in[3];
    const float* W1 = (const float*)d_in[4];  const float* b1 = (const float*)d_in[5];
    const float* W2 = (const float*)d_in[6];  const float* b2 = (const float*)d_in[7];
    const float* W3 = (const float*)d_in[8];  const float* b3 = (const float*)d_in[9];
    const float* W4 = (const float*)d_in[10]; const float* b4 = (const float*)d_in[11];
    const float* W5 = (const float*)d_in[12]; const float* b5 = (const float*)d_in[13];
    const float* W6 = (const float*)d_in[14]; const float* b6 = (const float*)d_in[15];
    const float* W7 = (const float*)d_in[16]; const float* b7 = (const float*)d_in[17];

    int B = in_sizes[0] / 9;

    prep_all<<<(7 * 16384 + 255) / 256, 256>>>(W1, W2, W3, W4, W5, W6, W7,
                                               b1, b2, b3, b4, b5, b6, b7);

    cudaFuncSetAttribute(stress_main,
                         cudaFuncAttributeMaxDynamicSharedMemorySize, SMEM_TOTAL);

    int grid = (B + TILE_M - 1) / TILE_M;
    stress_main<<<grid, THREADS, SMEM_TOTAL>>>(F, C, traj, latent, (float*)d_out, B);
}

// round 13
// speedup vs baseline: 1.2423x; 1.2423x over previous
#include <cuda_runtime.h>
#include <cuda_bf16.h>
#include <stdint.h>

// ============================================================================
// StressNN on GB300 (sm_103a, plain sm_103 PTX target -> HMMA path)
//   R13 = R12 token ring + FIX2: intra-group barriers for A (bar 5) and
//   B (bar 6) between MMA(l) and epilogue(l) — bar.arrive is non-blocking, so
//   without these a fast warp's epilogue overwrites X rows a slow sibling
//   warp's MMA is still reading.
//   Ring: A-MMA -> tok1 -> [barA] epiA  ||  B-MMA -> tok2 -> [barB] epiB ||
//         C-MMA -> [barC] refill W -> tok3 -> epiC
// ============================================================================

#define TILE_M   96
#define THREADS  384

#define OFF_XHI    0
#define OFF_XLO    24576
#define OFF_W      49152
#define SMEM_TOTAL 114688
#define XCHUNK     12288
#define XLO_DELTA  24576
#define WCHUNK     16384
#define WLO_DELTA  32768

__device__ __align__(16) unsigned char g_wimg[7 * 65536];
__device__ float g_bias[7 * 128];

// ---------------------------------------------------------------------------
__device__ __forceinline__ uint32_t smem_u32(const void* p) {
    uint32_t a;
    asm("{ .reg .u64 t; cvta.to.shared.u64 t, %1; cvt.u32.u64 %0, t; }"
        : "=r"(a) : "l"(p));
    return a;
}

#define LDSM_X4(r0, r1, r2, r3, a) \
    asm volatile("ldmatrix.sync.aligned.m8n8.x4.shared.b16 {%0,%1,%2,%3}, [%4];" \
                 : "=r"(r0), "=r"(r1), "=r"(r2), "=r"(r3) : "r"(a))

#define MMA_BF16(c, a, b) \
    asm volatile("mma.sync.aligned.m16n8k16.row.col.f32.bf16.bf16.f32 " \
                 "{%0,%1,%2,%3},{%4,%5,%6,%7},{%8,%9},{%0,%1,%2,%3};" \
                 : "+f"((c)[0]), "+f"((c)[1]), "+f"((c)[2]), "+f"((c)[3]) \
                 : "r"((a)[0]), "r"((a)[1]), "r"((a)[2]), "r"((a)[3]), \
                   "r"((b)[0]), "r"((b)[1]))

#define CP_ASYNC16(dst, src) \
    asm volatile("cp.async.cg.shared.global [%0], [%1], 16;" \
                 :: "r"(dst), "l"(src) : "memory")
#define CP_COMMIT() asm volatile("cp.async.commit_group;" ::: "memory")
#define CP_WAIT0()  asm volatile("cp.async.wait_group 0;" ::: "memory")

#define STS32(a, v) \
    asm volatile("st.shared.b32 [%0], %1;" :: "r"(a), "r"(v) : "memory")

// named-barrier token passing: producer group arrives, consumer group syncs
#define NBAR_SYNC(id) \
    asm volatile("bar.sync %0, 256;" :: "r"(id) : "memory")
#define NBAR_ARRIVE(id) \
    asm volatile("bar.arrive %0, 256;" :: "r"(id) : "memory")
// intra-group barriers (4 warps = 128 threads each)
#define NBAR_GRP(id) \
    asm volatile("bar.sync %0, 128;" :: "r"(id) : "memory")

// split two floats into bf16x2 hi word + bf16x2 lo word
__device__ __forceinline__ void split_pack(float a0, float a1,
                                           uint32_t& hi, uint32_t& lo) {
    uint32_t h;
    asm("cvt.rn.bf16x2.f32 %0, %1, %2;" : "=r"(h) : "f"(a1), "f"(a0));
    float h0 = __uint_as_float(h << 16);
    float h1 = __uint_as_float(h & 0xFFFF0000u);
    float l0 = a0 - h0;
    float l1 = a1 - h1;
    asm("cvt.rn.bf16x2.f32 %0, %1, %2;" : "=r"(lo) : "f"(l1), "f"(l0));
    hi = h;
}

// erf via Abramowitz-Stegun 7.1.26 (|eps| <= 1.5e-7), branch-free
__device__ __forceinline__ float erf_fast(float x) {
    float ax = fabsf(x);
    float t = __frcp_rn(fmaf(0.3275911f, ax, 1.0f));
    float y = t * fmaf(t, fmaf(t, fmaf(t, fmaf(t, 1.061405429f, -1.453152027f),
                                       1.421413741f), -0.284496736f), 0.254829592f);
    float r = 1.0f - y * __expf(-ax * ax);
    return copysignf(r, x);
}

__device__ __forceinline__ float gelu_exact(float x) {
    return 0.5f * x * (1.0f + erf_fast(x * 0.70710678118654752f));
}

// ---------------------------------------------------------------------------
// prep kernel: bf16 hi/lo split, pre-swizzled SW128 W^T tile images + bias
// ---------------------------------------------------------------------------
__global__ void prep_all(const float* __restrict__ w1, const float* __restrict__ w2,
                         const float* __restrict__ w3, const float* __restrict__ w4,
                         const float* __restrict__ w5, const float* __restrict__ w6,
                         const float* __restrict__ w7,
                         const float* __restrict__ b1, const float* __restrict__ b2,
                         const float* __restrict__ b3, const float* __restrict__ b4,
                         const float* __restrict__ b5, const float* __restrict__ b6,
                         const float* __restrict__ b7) {
    int idx = blockIdx.x * blockDim.x + threadIdx.x;
    if (idx < 7 * 16384) {
        int l = idx >> 14;
        int rem = idx & 16383;
        int n = rem >> 7;
        int k = rem & 127;
        int K = (l == 0) ? 89 : 128;
        int N = (l == 6) ? 9 : 128;
        const float* w;
        switch (l) {
            case 0: w = w1; break; case 1: w = w2; break; case 2: w = w3; break;
            case 3: w = w4; break; case 4: w = w5; break; case 5: w = w6; break;
            default: w = w7; break;
        }
        float v = 0.f;
        if (k < K && n < N) v = w[k * N + n];
        __nv_bfloat16 hi = __float2bfloat16(v);
        __nv_bfloat16 lo = __float2bfloat16(v - __bfloat162float(hi));
        size_t off = (size_t)l * 65536 + (size_t)(k >> 6) * 16384 +
                     (uint32_t)(n * 128 + (((k & 63) * 2) ^ ((n & 7) << 4)));
        *(__nv_bfloat16*)(g_wimg + off)         = hi;
        *(__nv_bfloat16*)(g_wimg + off + 32768) = lo;
    }
    if (idx < 7 * 128) {
        int l = idx >> 7;
        int n = idx & 127;
        const float* b;
        switch (l) {
            case 0: b = b1; break; case 1: b = b2; break; case 2: b = b3; break;
            case 3: b = b4; break; case 4: b = b5; break; case 5: b = b6; break;
            default: b = b7; break;
        }
        int N = (l == 6) ? 9 : 128;
        g_bias[idx] = (n < N) ? b[n] : 0.f;
    }
}

// ---------------------------------------------------------------------------
// templated MMA body: KSTEPS k-slices, 2 m-tiles, 4 n-tiles
// ---------------------------------------------------------------------------
template <int KSTEPS>
__device__ __forceinline__ void mma_layer(float (&acc)[2][4][4],
                                          uint32_t abase, uint32_t wbase4,
                                          uint32_t kA, uint32_t kB, uint32_t rsw) {
    #pragma unroll
    for (int ks = 0; ks < KSTEPS; ++ks) {
        uint32_t koffA = ((((uint32_t)ks * 16 + kA) & 63) << 1) ^ rsw;
        uint32_t koffB = ((((uint32_t)ks * 16 + kB) & 63) << 1) ^ rsw;
        uint32_t achunk = (uint32_t)(ks >> 2) * XCHUNK;
        uint32_t wchunk = (uint32_t)(ks >> 2) * WCHUNK;

        uint32_t bh[8], bl[8];
        #pragma unroll
        for (int p = 0; p < 2; ++p) {
            uint32_t ba = wbase4 + (uint32_t)p * 2048 + wchunk + koffB;
            LDSM_X4(bh[p*4+0], bh[p*4+1], bh[p*4+2], bh[p*4+3], ba);
            LDSM_X4(bl[p*4+0], bl[p*4+1], bl[p*4+2], bl[p*4+3], ba + WLO_DELTA);
        }
        #pragma unroll
        for (int mt = 0; mt < 2; ++mt) {
            uint32_t aa = abase + (uint32_t)mt * 2048 + achunk + koffA;
            uint32_t ah[4], al[4];
            LDSM_X4(ah[0], ah[1], ah[2], ah[3], aa);
            LDSM_X4(al[0], al[1], al[2], al[3], aa + XLO_DELTA);
            #pragma unroll
            for (int nt = 0; nt < 4; ++nt) {
                MMA_BF16(acc[mt][nt], ah, bh + nt * 2);
                MMA_BF16(acc[mt][nt], ah, bl + nt * 2);
                MMA_BF16(acc[mt][nt], al, bh + nt * 2);
            }
        }
    }
}

// ---------------------------------------------------------------------------
// main fused kernel: one CTA = 96 particles; 12 warps = 3 groups x 4 warps,
// warp tile m32 x n32. Token ring A->B->C->A via named barriers 1/2/3.
// ---------------------------------------------------------------------------
__global__ void __launch_bounds__(THREADS, 2)
stress_main(const float* __restrict__ F, const float* __restrict__ C,
            const int* __restrict__ traj_id, const float* __restrict__ latent,
            float* __restrict__ out, int Bn) {
    extern __shared__ char smem[];
    const uint32_t sb = smem_u32(smem);
    const int t    = threadIdx.x;
    const int wid  = t >> 5;
    const int lane = t & 31;
    const int mband = wid >> 2;       // group id: 0=A, 1=B, 2=C
    const int nband = wid & 3;
    const int g     = lane >> 2;
    const int tid4  = lane & 3;

    const size_t base = (size_t)blockIdx.x * TILE_M;
    const int valid = min(TILE_M, Bn - (int)base);

    // W[0] prefetch (65536 B)
    {
        const char* wsrc = (const char*)g_wimg;
        for (int i = t; i < 4096; i += THREADS)
            CP_ASYNC16(sb + OFF_W + (uint32_t)i * 16, wsrc + (size_t)i * 16);
        CP_COMMIT();
    }

    // stage F, C coalesced into X_lo scratch
    {
        const float* Fg = F + base * 9;
        const float* Cg = C + base * 9;
        float* s1 = (float*)(smem + OFF_XLO);
        float* s2 = (float*)(smem + OFF_XLO + 4608);
        int lim = valid * 9;
        for (int i = t; i < lim; i += THREADS) { s1[i] = Fg[i]; s2[i] = Cg[i]; }
    }
    __syncthreads();

    float f[9], c9[9];
    if (t < TILE_M) {
        if (t < valid) {
            const float* s1 = (const float*)(smem + OFF_XLO);
            const float* s2 = (const float*)(smem + OFF_XLO + 4608);
            #pragma unroll
            for (int i = 0; i < 9; ++i) { f[i] = s1[t * 9 + i]; c9[i] = s2[t * 9 + i]; }
        } else {
            #pragma unroll
            for (int i = 0; i < 9; ++i) { f[i] = (i % 4 == 0) ? 1.f : 0.f; c9[i] = 0.f; }
        }
    }
    __syncthreads();

    // ---- features: thread t (< 96) owns row t ----
    if (t < TILE_M) {
        const int traj = traj_id[0];
        const float* latp = latent + (size_t)traj * 64;
        float fe[16];
        #pragma unroll
        for (int i = 0; i < 3; ++i)
            #pragma unroll
            for (int k = 0; k < 3; ++k)
                fe[i * 3 + k] = f[i*3+0]*f[k*3+0] + f[i*3+1]*f[k*3+1] + f[i*3+2]*f[k*3+2];
        float det = f[0]*(f[4]*f[8]-f[5]*f[7]) - f[1]*(f[3]*f[8]-f[5]*f[6])
                  + f[2]*(f[3]*f[7]-f[4]*f[6]);
        float J  = fmaxf(det, 1e-6f);
        float J1 = fmaxf(f[0], 1e-6f);
        float a00 = fe[0], a01 = fe[1], a02 = fe[2], a11 = fe[4], a12 = fe[5], a22 = fe[8];
        float q  = (a00 + a11 + a22) * (1.f / 3.f);
        float p1 = a01*a01 + a02*a02 + a12*a12;
        float d0 = a00 - q, d1 = a11 - q, d2 = a22 - q;
        float p2 = d0*d0 + d1*d1 + d2*d2 + 2.f*p1;
        float pp = sqrtf(fmaxf(p2 * (1.f / 6.f), 0.f));
        float ip = 1.f / fmaxf(pp, 1e-20f);
        float b00 = d0*ip, b01 = a01*ip, b02 = a02*ip;
        float b11 = d1*ip, b12 = a12*ip, b22 = d2*ip;
        float detB = b00*(b11*b22 - b12*b12) - b01*(b01*b22 - b12*b02)
                   + b02*(b01*b12 - b11*b02);
        float r = fminf(fmaxf(0.5f * detB, -1.f), 1.f);
        float phi = acosf(r) * (1.f / 3.f);
        float e1 = q + 2.f * pp * cosf(phi);
        float e3 = q + 2.f * pp * cosf(phi + 2.0943951023931953f);
        float e2 = 3.f * q - e1 - e3;
        fe[9]  = logf(J);
        fe[10] = sqrtf(fmaxf(e1, 0.f));
        fe[11] = sqrtf(fmaxf(e2, 0.f));
        fe[12] = sqrtf(fmaxf(e3, 0.f));
        fe[13] = J;
        fe[14] = logf(J1);
        fe[15] = J1;

        uint32_t rowbase = sb + OFF_XHI + (uint32_t)t * 128;
        uint32_t rsw0 = (uint32_t)(t & 7) << 4;
        #pragma unroll
        for (int n = 0; n < 128; n += 2) {
            #define CVAL(nn) ((nn) < 16 ? fe[(nn)] : ((nn) < 25 ? c9[(nn)-16] : \
                              ((nn) < 89 ? __ldg(latp + (nn)-25) : 0.f)))
            float v0 = CVAL(n);
            float v1 = CVAL(n + 1);
            #undef CVAL
            uint32_t hi, lo;
            split_pack(v0, v1, hi, lo);
            uint32_t a = rowbase + (uint32_t)((n >> 6) * XCHUNK)
                       + (((uint32_t)(n & 63) << 1) ^ rsw0);
            STS32(a, hi);
            STS32(a + XLO_DELTA, lo);
        }
    }
    CP_WAIT0();
    __syncthreads();   // X[0] + W[0] ready

    // ---- per-lane constants ----
    const uint32_t rsw   = (uint32_t)(lane & 7) << 4;
    const uint32_t kA    = (lane & 16) ? 8u : 0u;
    const uint32_t kB    = (uint32_t)(lane & 8);
    const uint32_t abase = sb + OFF_XHI + (uint32_t)(mband * 32 + (lane & 15)) * 128;
    const uint32_t wbase4 = sb + OFF_W +
        (uint32_t)(nband * 32 + (lane & 7) + (((uint32_t)lane >> 4) << 3)) * 128;
    const uint32_t erow  = sb + OFF_XHI + (uint32_t)(mband * 32 + g) * 128;
    const int      cbase = nband * 32 + tid4 * 2;
    const uint32_t echunk = (uint32_t)(nband >> 1) * XCHUNK;
    const uint32_t egsw   = (uint32_t)g << 4;

    // ================= layers 0..5: token ring =================
    #pragma unroll 1
    for (int l = 0; l < 6; ++l) {
        // ---- wait for tensor token ----
        if (mband == 0)      { if (l > 0) NBAR_SYNC(3); }
        else if (mband == 1) { NBAR_SYNC(1); }
        else                 { NBAR_SYNC(2); }

        float acc[2][4][4];
        {
            const float* gb = g_bias + l * 128;
            #pragma unroll
            for (int nt = 0; nt < 4; ++nt) {
                float b0 = __ldg(gb + cbase + nt * 8);
                float b1 = __ldg(gb + cbase + nt * 8 + 1);
                #pragma unroll
                for (int mt = 0; mt < 2; ++mt) {
                    acc[mt][nt][0] = b0; acc[mt][nt][1] = b1;
                    acc[mt][nt][2] = b0; acc[mt][nt][3] = b1;
                }
            }
        }
        if (l == 0) mma_layer<6>(acc, abase, wbase4, kA, kB, rsw);
        else        mma_layer<8>(acc, abase, wbase4, kA, kB, rsw);

        // ---- pass token; intra-group sync before epilogue overwrites X ----
        if (mband == 0) {
            NBAR_ARRIVE(1);
            NBAR_GRP(5);   // all A warps done reading X rows A before overwrite
        } else if (mband == 1) {
            NBAR_ARRIVE(2);
            NBAR_GRP(6);   // all B warps done reading X rows B before overwrite
        } else {
            NBAR_GRP(4);   // all C warps done reading W(l) AND X rows C
            const char* wsrc = (const char*)(g_wimg + (size_t)(l + 1) * 65536);
            int lt = t - 256;   // 0..127 within group C
            for (int i = lt; i < 4096; i += 128)
                CP_ASYNC16(sb + OFF_W + (uint32_t)i * 16, wsrc + (size_t)i * 16);
            CP_COMMIT();
            CP_WAIT0();
            if (l < 5) NBAR_ARRIVE(3);   // token (+ W ready) to group A
        }

        // ---- epilogue: GELU + split + store own rows back to X ----
        #pragma unroll
        for (int mt = 0; mt < 2; ++mt) {
            uint32_t rb0 = erow + (uint32_t)mt * 2048;
            uint32_t rb1 = rb0 + 1024;
            #pragma unroll
            for (int nt = 0; nt < 4; ++nt) {
                int c = cbase + nt * 8;
                float x00 = gelu_exact(acc[mt][nt][0]);
                float x01 = gelu_exact(acc[mt][nt][1]);
                float x10 = gelu_exact(acc[mt][nt][2]);
                float x11 = gelu_exact(acc[mt][nt][3]);
                uint32_t h0, l0, h1, l1;
                split_pack(x00, x01, h0, l0);
                split_pack(x10, x11, h1, l1);
                uint32_t coff = echunk + ((((uint32_t)(c & 63)) << 1) ^ egsw);
                STS32(rb0 + coff, h0);
                STS32(rb0 + coff + XLO_DELTA, l0);
                STS32(rb1 + coff, h1);
                STS32(rb1 + coff + XLO_DELTA, l1);
            }
        }
    }
    __syncthreads();   // X(6) from all groups + W6 visible

    // ================= layer 6 (N=16; nband==0 warps of each group) ==========
    float acc6[2][2][4];
    if (nband == 0) {
        const float* gb = g_bias + 6 * 128;
        #pragma unroll
        for (int nt = 0; nt < 2; ++nt) {
            float b0 = __ldg(gb + tid4 * 2 + nt * 8);
            float b1 = __ldg(gb + tid4 * 2 + nt * 8 + 1);
            #pragma unroll
            for (int mt = 0; mt < 2; ++mt) {
                acc6[mt][nt][0] = b0; acc6[mt][nt][1] = b1;
                acc6[mt][nt][2] = b0; acc6[mt][nt][3] = b1;
            }
        }
        #pragma unroll
        for (int ks = 0; ks < 8; ++ks) {
            uint32_t koffA = ((((uint32_t)ks * 16 + kA) & 63) << 1) ^ rsw;
            uint32_t koffB = ((((uint32_t)ks * 16 + kB) & 63) << 1) ^ rsw;
            uint32_t achunk = (uint32_t)(ks >> 2) * XCHUNK;
            uint32_t wchunk = (uint32_t)(ks >> 2) * WCHUNK;

            uint32_t bh[4], bl[4];
            uint32_t ba = wbase4 + wchunk + koffB;
            LDSM_X4(bh[0], bh[1], bh[2], bh[3], ba);
            LDSM_X4(bl[0], bl[1], bl[2], bl[3], ba + WLO_DELTA);
            #pragma unroll
            for (int mt = 0; mt < 2; ++mt) {
                uint32_t aa = abase + (uint32_t)mt * 2048 + achunk + koffA;
                uint32_t ah[4], al[4];
                LDSM_X4(ah[0], ah[1], ah[2], ah[3], aa);
                LDSM_X4(al[0], al[1], al[2], al[3], aa + XLO_DELTA);
                #pragma unroll
                for (int nt = 0; nt < 2; ++nt) {
                    MMA_BF16(acc6[mt][nt], ah, bh + nt * 2);
                    MMA_BF16(acc6[mt][nt], ah, bl + nt * 2);
                    MMA_BF16(acc6[mt][nt], al, bh + nt * 2);
                }
            }
        }
    }
    __syncthreads();   // X reads done -> X_lo reusable as staging

    float* stag = (float*)(smem + OFF_XLO);
    if (nband == 0) {
        #pragma unroll
        for (int mt = 0; mt < 2; ++mt) {
            int r0 = mband * 32 + mt * 16 + g;
            #pragma unroll
            for (int nt = 0; nt < 2; ++nt) {
                int c = nt * 8 + tid4 * 2;
                if (c < 9) {
                    stag[r0 * 12 + c]       = acc6[mt][nt][0];
                    stag[(r0 + 8) * 12 + c] = acc6[mt][nt][2];
                }
                if (c + 1 < 9) {
                    stag[r0 * 12 + c + 1]       = acc6[mt][nt][1];
                    stag[(r0 + 8) * 12 + c + 1] = acc6[mt][nt][3];
                }
            }
        }
    }
    __syncthreads();

    float* stag2 = (float*)(smem + OFF_XLO + 8192);
    if (t < TILE_M) {
        float o[9];
        #pragma unroll
        for (int j = 0; j < 9; ++j) o[j] = stag[t * 12 + j];
        float s01 = 0.5f * (o[1] + o[3]);
        float s02 = 0.5f * (o[2] + o[6]);
        float s12 = 0.5f * (o[5] + o[7]);
        float* d = stag2 + t * 9;
        d[0] = o[0]; d[1] = s01; d[2] = s02;
        d[3] = s01;  d[4] = o[4]; d[5] = s12;
        d[6] = s02;  d[7] = s12;  d[8] = o[8];
    }
    __syncthreads();
    {
        float* og = out + base * 9;
        int lim = valid * 9;
        for (int i = t; i < lim; i += THREADS) og[i] = stag2[i];
    }
}

// ---------------------------------------------------------------------------
extern "C" void kernel_launch(void* const* d_in, const int* in_sizes, int n_in,
                              void* d_out, int out_size) {
    const float* F      = (const float*)d_in[0];
    const float* C      = (const float*)d_in[1];
    const int*   traj   = (const int*)d_in[2];
    const float* latent = (const float*)d_in[3];
    const float* W1 = (const float*)d_in[4];  const float* b1 = (const float*)d_in[5];
    const float* W2 = (const float*)d_in[6];  const float* b2 = (const float*)d_in[7];
    const float* W3 = (const float*)d_in[8];  const float* b3 = (const float*)d_in[9];
    const float* W4 = (const float*)d_in[10]; const float* b4 = (const float*)d_in[11];
    const float* W5 = (const float*)d_in[12]; const float* b5 = (const float*)d_in[13];
    const float* W6 = (const float*)d_in[14]; const float* b6 = (const float*)d_in[15];
    const float* W7 = (const float*)d_in[16]; const float* b7 = (const float*)d_in[17];

    int B = in_sizes[0] / 9;

    prep_all<<<(7 * 16384 + 255) / 256, 256>>>(W1, W2, W3, W4, W5, W6, W7,
                                               b1, b2, b3, b4, b5, b6, b7);

    cudaFuncSetAttribute(stress_main,
                         cudaFuncAttributeMaxDynamicSharedMemorySize, SMEM_TOTAL);

    int grid = (B + TILE_M - 1) / TILE_M;
    stress_main<<<grid, THREADS, SMEM_TOTAL>>>(F, C, traj, latent, (float*)d_out, B);
}

// round 14
// speedup vs baseline: 1.2459x; 1.0029x over previous
#include <cuda_runtime.h>
#include <cuda_bf16.h>
#include <stdint.h>

// ============================================================================
// StressNN on GB300 (sm_103a, plain sm_103 PTX target -> HMMA path)
//   R14 = R13 (token ring, correct) + MMA RAW-chain breaking:
//   per k-slice, MMAs are emitted grouped by split term (hh x8, hl x8, lh x8)
//   so consecutive HMMAs hit different accumulators (RAW distance 8 instrs)
//   instead of 3 back-to-back dependent HMMAs on one accumulator.
// ============================================================================

#define TILE_M   96
#define THREADS  384

#define OFF_XHI    0
#define OFF_XLO    24576
#define OFF_W      49152
#define SMEM_TOTAL 114688
#define XCHUNK     12288
#define XLO_DELTA  24576
#define WCHUNK     16384
#define WLO_DELTA  32768

__device__ __align__(16) unsigned char g_wimg[7 * 65536];
__device__ float g_bias[7 * 128];

// ---------------------------------------------------------------------------
__device__ __forceinline__ uint32_t smem_u32(const void* p) {
    uint32_t a;
    asm("{ .reg .u64 t; cvta.to.shared.u64 t, %1; cvt.u32.u64 %0, t; }"
        : "=r"(a) : "l"(p));
    return a;
}

#define LDSM_X4(r0, r1, r2, r3, a) \
    asm volatile("ldmatrix.sync.aligned.m8n8.x4.shared.b16 {%0,%1,%2,%3}, [%4];" \
                 : "=r"(r0), "=r"(r1), "=r"(r2), "=r"(r3) : "r"(a))

#define MMA_BF16(c, a, b) \
    asm volatile("mma.sync.aligned.m16n8k16.row.col.f32.bf16.bf16.f32 " \
                 "{%0,%1,%2,%3},{%4,%5,%6,%7},{%8,%9},{%0,%1,%2,%3};" \
                 : "+f"((c)[0]), "+f"((c)[1]), "+f"((c)[2]), "+f"((c)[3]) \
                 : "r"((a)[0]), "r"((a)[1]), "r"((a)[2]), "r"((a)[3]), \
                   "r"((b)[0]), "r"((b)[1]))

#define CP_ASYNC16(dst, src) \
    asm volatile("cp.async.cg.shared.global [%0], [%1], 16;" \
                 :: "r"(dst), "l"(src) : "memory")
#define CP_COMMIT() asm volatile("cp.async.commit_group;" ::: "memory")
#define CP_WAIT0()  asm volatile("cp.async.wait_group 0;" ::: "memory")

#define STS32(a, v) \
    asm volatile("st.shared.b32 [%0], %1;" :: "r"(a), "r"(v) : "memory")

// named-barrier token passing: producer group arrives, consumer group syncs
#define NBAR_SYNC(id) \
    asm volatile("bar.sync %0, 256;" :: "r"(id) : "memory")
#define NBAR_ARRIVE(id) \
    asm volatile("bar.arrive %0, 256;" :: "r"(id) : "memory")
// intra-group barriers (4 warps = 128 threads each)
#define NBAR_GRP(id) \
    asm volatile("bar.sync %0, 128;" :: "r"(id) : "memory")

// split two floats into bf16x2 hi word + bf16x2 lo word
__device__ __forceinline__ void split_pack(float a0, float a1,
                                           uint32_t& hi, uint32_t& lo) {
    uint32_t h;
    asm("cvt.rn.bf16x2.f32 %0, %1, %2;" : "=r"(h) : "f"(a1), "f"(a0));
    float h0 = __uint_as_float(h << 16);
    float h1 = __uint_as_float(h & 0xFFFF0000u);
    float l0 = a0 - h0;
    float l1 = a1 - h1;
    asm("cvt.rn.bf16x2.f32 %0, %1, %2;" : "=r"(lo) : "f"(l1), "f"(l0));
    hi = h;
}

// erf via Abramowitz-Stegun 7.1.26 (|eps| <= 1.5e-7), branch-free
__device__ __forceinline__ float erf_fast(float x) {
    float ax = fabsf(x);
    float t = __frcp_rn(fmaf(0.3275911f, ax, 1.0f));
    float y = t * fmaf(t, fmaf(t, fmaf(t, fmaf(t, 1.061405429f, -1.453152027f),
                                       1.421413741f), -0.284496736f), 0.254829592f);
    float r = 1.0f - y * __expf(-ax * ax);
    return copysignf(r, x);
}

__device__ __forceinline__ float gelu_exact(float x) {
    return 0.5f * x * (1.0f + erf_fast(x * 0.70710678118654752f));
}

// ---------------------------------------------------------------------------
// prep kernel: bf16 hi/lo split, pre-swizzled SW128 W^T tile images + bias
// ---------------------------------------------------------------------------
__global__ void prep_all(const float* __restrict__ w1, const float* __restrict__ w2,
                         const float* __restrict__ w3, const float* __restrict__ w4,
                         const float* __restrict__ w5, const float* __restrict__ w6,
                         const float* __restrict__ w7,
                         const float* __restrict__ b1, const float* __restrict__ b2,
                         const float* __restrict__ b3, const float* __restrict__ b4,
                         const float* __restrict__ b5, const float* __restrict__ b6,
                         const float* __restrict__ b7) {
    int idx = blockIdx.x * blockDim.x + threadIdx.x;
    if (idx < 7 * 16384) {
        int l = idx >> 14;
        int rem = idx & 16383;
        int n = rem >> 7;
        int k = rem & 127;
        int K = (l == 0) ? 89 : 128;
        int N = (l == 6) ? 9 : 128;
        const float* w;
        switch (l) {
            case 0: w = w1; break; case 1: w = w2; break; case 2: w = w3; break;
            case 3: w = w4; break; case 4: w = w5; break; case 5: w = w6; break;
            default: w = w7; break;
        }
        float v = 0.f;
        if (k < K && n < N) v = w[k * N + n];
        __nv_bfloat16 hi = __float2bfloat16(v);
        __nv_bfloat16 lo = __float2bfloat16(v - __bfloat162float(hi));
        size_t off = (size_t)l * 65536 + (size_t)(k >> 6) * 16384 +
                     (uint32_t)(n * 128 + (((k & 63) * 2) ^ ((n & 7) << 4)));
        *(__nv_bfloat16*)(g_wimg + off)         = hi;
        *(__nv_bfloat16*)(g_wimg + off + 32768) = lo;
    }
    if (idx < 7 * 128) {
        int l = idx >> 7;
        int n = idx & 127;
        const float* b;
        switch (l) {
            case 0: b = b1; break; case 1: b = b2; break; case 2: b = b3; break;
            case 3: b = b4; break; case 4: b = b5; break; case 5: b = b6; break;
            default: b = b7; break;
        }
        int N = (l == 6) ? 9 : 128;
        g_bias[idx] = (n < N) ? b[n] : 0.f;
    }
}

// ---------------------------------------------------------------------------
// templated MMA body: KSTEPS k-slices, 2 m-tiles, 4 n-tiles.
// MMAs grouped by split term so consecutive HMMAs hit different accumulators.
// ---------------------------------------------------------------------------
template <int KSTEPS>
__device__ __forceinline__ void mma_layer(float (&acc)[2][4][4],
                                          uint32_t abase, uint32_t wbase4,
                                          uint32_t kA, uint32_t kB, uint32_t rsw) {
    #pragma unroll
    for (int ks = 0; ks < KSTEPS; ++ks) {
        uint32_t koffA = ((((uint32_t)ks * 16 + kA) & 63) << 1) ^ rsw;
        uint32_t koffB = ((((uint32_t)ks * 16 + kB) & 63) << 1) ^ rsw;
        uint32_t achunk = (uint32_t)(ks >> 2) * XCHUNK;
        uint32_t wchunk = (uint32_t)(ks >> 2) * WCHUNK;

        uint32_t bh[8], bl[8];
        #pragma unroll
        for (int p = 0; p < 2; ++p) {
            uint32_t ba = wbase4 + (uint32_t)p * 2048 + wchunk + koffB;
            LDSM_X4(bh[p*4+0], bh[p*4+1], bh[p*4+2], bh[p*4+3], ba);
            LDSM_X4(bl[p*4+0], bl[p*4+1], bl[p*4+2], bl[p*4+3], ba + WLO_DELTA);
        }
        uint32_t ah[2][4], al[2][4];
        #pragma unroll
        for (int mt = 0; mt < 2; ++mt) {
            uint32_t aa = abase + (uint32_t)mt * 2048 + achunk + koffA;
            LDSM_X4(ah[mt][0], ah[mt][1], ah[mt][2], ah[mt][3], aa);
            LDSM_X4(al[mt][0], al[mt][1], al[mt][2], al[mt][3], aa + XLO_DELTA);
        }
        // term 1: ah x bh (8 independent accumulators)
        #pragma unroll
        for (int mt = 0; mt < 2; ++mt)
            #pragma unroll
            for (int nt = 0; nt < 4; ++nt)
                MMA_BF16(acc[mt][nt], ah[mt], bh + nt * 2);
        // term 2: ah x bl
        #pragma unroll
        for (int mt = 0; mt < 2; ++mt)
            #pragma unroll
            for (int nt = 0; nt < 4; ++nt)
                MMA_BF16(acc[mt][nt], ah[mt], bl + nt * 2);
        // term 3: al x bh
        #pragma unroll
        for (int mt = 0; mt < 2; ++mt)
            #pragma unroll
            for (int nt = 0; nt < 4; ++nt)
                MMA_BF16(acc[mt][nt], al[mt], bh + nt * 2);
    }
}

// ---------------------------------------------------------------------------
// main fused kernel: one CTA = 96 particles; 12 warps = 3 groups x 4 warps,
// warp tile m32 x n32. Token ring A->B->C->A via named barriers 1/2/3.
// ---------------------------------------------------------------------------
__global__ void __launch_bounds__(THREADS, 2)
stress_main(const float* __restrict__ F, const float* __restrict__ C,
            const int* __restrict__ traj_id, const float* __restrict__ latent,
            float* __restrict__ out, int Bn) {
    extern __shared__ char smem[];
    const uint32_t sb = smem_u32(smem);
    const int t    = threadIdx.x;
    const int wid  = t >> 5;
    const int lane = t & 31;
    const int mband = wid >> 2;       // group id: 0=A, 1=B, 2=C
    const int nband = wid & 3;
    const int g     = lane >> 2;
    const int tid4  = lane & 3;

    const size_t base = (size_t)blockIdx.x * TILE_M;
    const int valid = min(TILE_M, Bn - (int)base);

    // W[0] prefetch (65536 B)
    {
        const char* wsrc = (const char*)g_wimg;
        for (int i = t; i < 4096; i += THREADS)
            CP_ASYNC16(sb + OFF_W + (uint32_t)i * 16, wsrc + (size_t)i * 16);
        CP_COMMIT();
    }

    // stage F, C coalesced into X_lo scratch
    {
        const float* Fg = F + base * 9;
        const float* Cg = C + base * 9;
        float* s1 = (float*)(smem + OFF_XLO);
        float* s2 = (float*)(smem + OFF_XLO + 4608);
        int lim = valid * 9;
        for (int i = t; i < lim; i += THREADS) { s1[i] = Fg[i]; s2[i] = Cg[i]; }
    }
    __syncthreads();

    float f[9], c9[9];
    if (t < TILE_M) {
        if (t < valid) {
            const float* s1 = (const float*)(smem + OFF_XLO);
            const float* s2 = (const float*)(smem + OFF_XLO + 4608);
            #pragma unroll
            for (int i = 0; i < 9; ++i) { f[i] = s1[t * 9 + i]; c9[i] = s2[t * 9 + i]; }
        } else {
            #pragma unroll
            for (int i = 0; i < 9; ++i) { f[i] = (i % 4 == 0) ? 1.f : 0.f; c9[i] = 0.f; }
        }
    }
    __syncthreads();

    // ---- features: thread t (< 96) owns row t ----
    if (t < TILE_M) {
        const int traj = traj_id[0];
        const float* latp = latent + (size_t)traj * 64;
        float fe[16];
        #pragma unroll
        for (int i = 0; i < 3; ++i)
            #pragma unroll
            for (int k = 0; k < 3; ++k)
                fe[i * 3 + k] = f[i*3+0]*f[k*3+0] + f[i*3+1]*f[k*3+1] + f[i*3+2]*f[k*3+2];
        float det = f[0]*(f[4]*f[8]-f[5]*f[7]) - f[1]*(f[3]*f[8]-f[5]*f[6])
                  + f[2]*(f[3]*f[7]-f[4]*f[6]);
        float J  = fmaxf(det, 1e-6f);
        float J1 = fmaxf(f[0], 1e-6f);
        float a00 = fe[0], a01 = fe[1], a02 = fe[2], a11 = fe[4], a12 = fe[5], a22 = fe[8];
        float q  = (a00 + a11 + a22) * (1.f / 3.f);
        float p1 = a01*a01 + a02*a02 + a12*a12;
        float d0 = a00 - q, d1 = a11 - q, d2 = a22 - q;
        float p2 = d0*d0 + d1*d1 + d2*d2 + 2.f*p1;
        float pp = sqrtf(fmaxf(p2 * (1.f / 6.f), 0.f));
        float ip = 1.f / fmaxf(pp, 1e-20f);
        float b00 = d0*ip, b01 = a01*ip, b02 = a02*ip;
        float b11 = d1*ip, b12 = a12*ip, b22 = d2*ip;
        float detB = b00*(b11*b22 - b12*b12) - b01*(b01*b22 - b12*b02)
                   + b02*(b01*b12 - b11*b02);
        float r = fminf(fmaxf(0.5f * detB, -1.f), 1.f);
        float phi = acosf(r) * (1.f / 3.f);
        float e1 = q + 2.f * pp * cosf(phi);
        float e3 = q + 2.f * pp * cosf(phi + 2.0943951023931953f);
        float e2 = 3.f * q - e1 - e3;
        fe[9]  = logf(J);
        fe[10] = sqrtf(fmaxf(e1, 0.f));
        fe[11] = sqrtf(fmaxf(e2, 0.f));
        fe[12] = sqrtf(fmaxf(e3, 0.f));
        fe[13] = J;
        fe[14] = logf(J1);
        fe[15] = J1;

        uint32_t rowbase = sb + OFF_XHI + (uint32_t)t * 128;
        uint32_t rsw0 = (uint32_t)(t & 7) << 4;
        #pragma unroll
        for (int n = 0; n < 128; n += 2) {
            #define CVAL(nn) ((nn) < 16 ? fe[(nn)] : ((nn) < 25 ? c9[(nn)-16] : \
                              ((nn) < 89 ? __ldg(latp + (nn)-25) : 0.f)))
            float v0 = CVAL(n);
            float v1 = CVAL(n + 1);
            #undef CVAL
            uint32_t hi, lo;
            split_pack(v0, v1, hi, lo);
            uint32_t a = rowbase + (uint32_t)((n >> 6) * XCHUNK)
                       + (((uint32_t)(n & 63) << 1) ^ rsw0);
            STS32(a, hi);
            STS32(a + XLO_DELTA, lo);
        }
    }
    CP_WAIT0();
    __syncthreads();   // X[0] + W[0] ready

    // ---- per-lane constants ----
    const uint32_t rsw   = (uint32_t)(lane & 7) << 4;
    const uint32_t kA    = (lane & 16) ? 8u : 0u;
    const uint32_t kB    = (uint32_t)(lane & 8);
    const uint32_t abase = sb + OFF_XHI + (uint32_t)(mband * 32 + (lane & 15)) * 128;
    const uint32_t wbase4 = sb + OFF_W +
        (uint32_t)(nband * 32 + (lane & 7) + (((uint32_t)lane >> 4) << 3)) * 128;
    const uint32_t erow  = sb + OFF_XHI + (uint32_t)(mband * 32 + g) * 128;
    const int      cbase = nband * 32 + tid4 * 2;
    const uint32_t echunk = (uint32_t)(nband >> 1) * XCHUNK;
    const uint32_t egsw   = (uint32_t)g << 4;

    // ================= layers 0..5: token ring =================
    #pragma unroll 1
    for (int l = 0; l < 6; ++l) {
        // ---- wait for tensor token ----
        if (mband == 0)      { if (l > 0) NBAR_SYNC(3); }
        else if (mband == 1) { NBAR_SYNC(1); }
        else                 { NBAR_SYNC(2); }

        float acc[2][4][4];
        {
            const float* gb = g_bias + l * 128;
            #pragma unroll
            for (int nt = 0; nt < 4; ++nt) {
                float b0 = __ldg(gb + cbase + nt * 8);
                float b1 = __ldg(gb + cbase + nt * 8 + 1);
                #pragma unroll
                for (int mt = 0; mt < 2; ++mt) {
                    acc[mt][nt][0] = b0; acc[mt][nt][1] = b1;
                    acc[mt][nt][2] = b0; acc[mt][nt][3] = b1;
                }
            }
        }
        if (l == 0) mma_layer<6>(acc, abase, wbase4, kA, kB, rsw);
        else        mma_layer<8>(acc, abase, wbase4, kA, kB, rsw);

        // ---- pass token; intra-group sync before epilogue overwrites X ----
        if (mband == 0) {
            NBAR_ARRIVE(1);
            NBAR_GRP(5);   // all A warps done reading X rows A before overwrite
        } else if (mband == 1) {
            NBAR_ARRIVE(2);
            NBAR_GRP(6);   // all B warps done reading X rows B before overwrite
        } else {
            NBAR_GRP(4);   // all C warps done reading W(l) AND X rows C
            const char* wsrc = (const char*)(g_wimg + (size_t)(l + 1) * 65536);
            int lt = t - 256;   // 0..127 within group C
            for (int i = lt; i < 4096; i += 128)
                CP_ASYNC16(sb + OFF_W + (uint32_t)i * 16, wsrc + (size_t)i * 16);
            CP_COMMIT();
            CP_WAIT0();
            if (l < 5) NBAR_ARRIVE(3);   // token (+ W ready) to group A
        }

        // ---- epilogue: GELU + split + store own rows back to X ----
        #pragma unroll
        for (int mt = 0; mt < 2; ++mt) {
            uint32_t rb0 = erow + (uint32_t)mt * 2048;
            uint32_t rb1 = rb0 + 1024;
            #pragma unroll
            for (int nt = 0; nt < 4; ++nt) {
                int c = cbase + nt * 8;
                float x00 = gelu_exact(acc[mt][nt][0]);
                float x01 = gelu_exact(acc[mt][nt][1]);
                float x10 = gelu_exact(acc[mt][nt][2]);
                float x11 = gelu_exact(acc[mt][nt][3]);
                uint32_t h0, l0, h1, l1;
                split_pack(x00, x01, h0, l0);
                split_pack(x10, x11, h1, l1);
                uint32_t coff = echunk + ((((uint32_t)(c & 63)) << 1) ^ egsw);
                STS32(rb0 + coff, h0);
                STS32(rb0 + coff + XLO_DELTA, l0);
                STS32(rb1 + coff, h1);
                STS32(rb1 + coff + XLO_DELTA, l1);
            }
        }
    }
    __syncthreads();   // X(6) from all groups + W6 visible

    // ================= layer 6 (N=16; nband==0 warps of each group) ==========
    float acc6[2][2][4];
    if (nband == 0) {
        const float* gb = g_bias + 6 * 128;
        #pragma unroll
        for (int nt = 0; nt < 2; ++nt) {
            float b0 = __ldg(gb + tid4 * 2 + nt * 8);
            float b1 = __ldg(gb + tid4 * 2 + nt * 8 + 1);
            #pragma unroll
            for (int mt = 0; mt < 2; ++mt) {
                acc6[mt][nt][0] = b0; acc6[mt][nt][1] = b1;
                acc6[mt][nt][2] = b0; acc6[mt][nt][3] = b1;
            }
        }
        #pragma unroll
        for (int ks = 0; ks < 8; ++ks) {
            uint32_t koffA = ((((uint32_t)ks * 16 + kA) & 63) << 1) ^ rsw;
            uint32_t koffB = ((((uint32_t)ks * 16 + kB) & 63) << 1) ^ rsw;
            uint32_t achunk = (uint32_t)(ks >> 2) * XCHUNK;
            uint32_t wchunk = (uint32_t)(ks >> 2) * WCHUNK;

            uint32_t bh[4], bl[4];
            uint32_t ba = wbase4 + wchunk + koffB;
            LDSM_X4(bh[0], bh[1], bh[2], bh[3], ba);
            LDSM_X4(bl[0], bl[1], bl[2], bl[3], ba + WLO_DELTA);
            uint32_t ah[2][4], al[2][4];
            #pragma unroll
            for (int mt = 0; mt < 2; ++mt) {
                uint32_t aa = abase + (uint32_t)mt * 2048 + achunk + koffA;
                LDSM_X4(ah[mt][0], ah[mt][1], ah[mt][2], ah[mt][3], aa);
                LDSM_X4(al[mt][0], al[mt][1], al[mt][2], al[mt][3], aa + XLO_DELTA);
            }
            #pragma unroll
            for (int mt = 0; mt < 2; ++mt)
                #pragma unroll
                for (int nt = 0; nt < 2; ++nt)
                    MMA_BF16(acc6[mt][nt], ah[mt], bh + nt * 2);
            #pragma unroll
            for (int mt = 0; mt < 2; ++mt)
                #pragma unroll
                for (int nt = 0; nt < 2; ++nt)
                    MMA_BF16(acc6[mt][nt], ah[mt], bl + nt * 2);
            #pragma unroll
            for (int mt = 0; mt < 2; ++mt)
                #pragma unroll
                for (int nt = 0; nt < 2; ++nt)
                    MMA_BF16(acc6[mt][nt], al[mt], bh + nt * 2);
        }
    }
    __syncthreads();   // X reads done -> X_lo reusable as staging

    float* stag = (float*)(smem + OFF_XLO);
    if (nband == 0) {
        #pragma unroll
        for (int mt = 0; mt < 2; ++mt) {
            int r0 = mband * 32 + mt * 16 + g;
            #pragma unroll
            for (int nt = 0; nt < 2; ++nt) {
                int c = nt * 8 + tid4 * 2;
                if (c < 9) {
                    stag[r0 * 12 + c]       = acc6[mt][nt][0];
                    stag[(r0 + 8) * 12 + c] = acc6[mt][nt][2];
                }
                if (c + 1 < 9) {
                    stag[r0 * 12 + c + 1]       = acc6[mt][nt][1];
                    stag[(r0 + 8) * 12 + c + 1] = acc6[mt][nt][3];
                }
            }
        }
    }
    __syncthreads();

    float* stag2 = (float*)(smem + OFF_XLO + 8192);
    if (t < TILE_M) {
        float o[9];
        #pragma unroll
        for (int j = 0; j < 9; ++j) o[j] = stag[t * 12 + j];
        float s01 = 0.5f * (o[1] + o[3]);
        float s02 = 0.5f * (o[2] + o[6]);
        float s12 = 0.5f * (o[5] + o[7]);
        float* d = stag2 + t * 9;
        d[0] = o[0]; d[1] = s01; d[2] = s02;
        d[3] = s01;  d[4] = o[4]; d[5] = s12;
        d[6] = s02;  d[7] = s12;  d[8] = o[8];
    }
    __syncthreads();
    {
        float* og = out + base * 9;
        int lim = valid * 9;
        for (int i = t; i < lim; i += THREADS) og[i] = stag2[i];
    }
}

// ---------------------------------------------------------------------------
extern "C" void kernel_launch(void* const* d_in, const int* in_sizes, int n_in,
                              void* d_out, int out_size) {
    const float* F      = (const float*)d_in[0];
    const float* C      = (const float*)d_in[1];
    const int*   traj   = (const int*)d_in[2];
    const float* latent = (const float*)d_in[3];
    const float* W1 = (const float*)d_in[4];  const float* b1 = (const float*)d_in[5];
    const float* W2 = (const float*)d_in[6];  const float* b2 = (const float*)d_in[7];
    const float* W3 = (const float*)d_in[8];  const float* b3 = (const float*)d_in[9];
    const float* W4 = (const float*)d_in[10]; const float* b4 = (const float*)d_in[11];
    const float* W5 = (const float*)d_in[12]; const float* b5 = (const float*)d_in[13];
    const float* W6 = (const float*)d_in[14]; const float* b6 = (const float*)d_in[15];
    const float* W7 = (const float*)d_in[16]; const float* b7 = (const float*)d_in[17];

    int B = in_sizes[0] / 9;

    prep_all<<<(7 * 16384 + 255) / 256, 256>>>(W1, W2, W3, W4, W5, W6, W7,
                                               b1, b2, b3, b4, b5, b6, b7);

    cudaFuncSetAttribute(stress_main,
                         cudaFuncAttributeMaxDynamicSharedMemorySize, SMEM_TOTAL);

    int grid = (B + TILE_M - 1) / TILE_M;
    stress_main<<<grid, THREADS, SMEM_TOTAL>>>(F, C, traj, latent, (float*)d_out, B);
}